// round 3
// baseline (speedup 1.0000x reference)
#include <cuda_runtime.h>

// RankingLoss, N=16384.
// loss = (1/N) * sum_i [ cnt_i>0 ? (sum_{j: t_j<t_i} max(0, 0.1 - (p_i - p_j))) / cnt_i : 0 ]
//
// Pipeline (3 kernels):
//   1. sort_kernel  (1 block): bucket-rank by target (targets ~ U[0,1)) ->
//      g_ps[r] = pred of the r-th smallest target. Exact within-bucket rank,
//      order-invariant -> deterministic.
//   2. pair_kernel  (triangular sweep): row r sums max(0, margin - p_r + p_k)
//      over k < r. cnt_r == r.
//   3. reduce_kernel (1 block): per-row loss + global mean.

#define NN 16384
#define NBUCK 16384
#define TPB 256
#define CH 1024
#define NCHUNK (NN / CH)        // 16
#define NBLKROW (NN / TPB)      // 64
#define STPB 1024               // sort/reduce block size
#define MARGIN 0.1f

__device__ int   g_count[NBUCK];
__device__ int   g_cursor[NBUCK];
__device__ int   g_offsets[NBUCK + 1];
__device__ int   g_members[NN];
__device__ float g_ps[NN];                  // pred in target-sorted order
__device__ float g_part[NCHUNK][NN];        // per-(chunk,row) hinge partials

__device__ __forceinline__ int bucket_of(float t) {
    int b = (int)(t * (float)NBUCK);
    b = b < 0 ? 0 : (b > NBUCK - 1 ? NBUCK - 1 : b);
    return b;
}

// ---- K1: full bucket-rank sort, one block ----
__global__ void __launch_bounds__(STPB)
sort_kernel(const float* __restrict__ pred, const float* __restrict__ target) {
    __shared__ int ssum[STPB];
    const int t = threadIdx.x;

    // Phase 1: zero counts + cursors (int4 stores).
    {
        int4* c4 = reinterpret_cast<int4*>(g_count);
        int4* u4 = reinterpret_cast<int4*>(g_cursor);
        int4 z = make_int4(0, 0, 0, 0);
#pragma unroll
        for (int k = t; k < NBUCK / 4; k += STPB) { c4[k] = z; u4[k] = z; }
    }
    __syncthreads();

    // Phase 2: histogram.
#pragma unroll
    for (int e = t; e < NN; e += STPB)
        atomicAdd(&g_count[bucket_of(target[e])], 1);
    __syncthreads();

    // Phase 3: exclusive prefix over 16384 counts.
    {
        const int base = t * 16;
        int loc[16];
        int s = 0;
#pragma unroll
        for (int k = 0; k < 16; k++) { loc[k] = g_count[base + k]; s += loc[k]; }
        ssum[t] = s;
        __syncthreads();
#pragma unroll
        for (int off = 1; off < STPB; off <<= 1) {
            int v = (t >= off) ? ssum[t - off] : 0;
            __syncthreads();
            ssum[t] += v;
            __syncthreads();
        }
        int run = ssum[t] - s;
#pragma unroll
        for (int k = 0; k < 16; k++) { g_offsets[base + k] = run; run += loc[k]; }
        if (t == STPB - 1) g_offsets[NBUCK] = run;
    }
    __syncthreads();

    // Phase 4: scatter member indices into bucket segments (order arbitrary).
#pragma unroll
    for (int e = t; e < NN; e += STPB) {
        int b = bucket_of(target[e]);
        int pos = g_offsets[b] + atomicAdd(&g_cursor[b], 1);
        g_members[pos] = e;
    }
    __syncthreads();

    // Phase 5: exact rank (order-invariant => deterministic), scatter preds.
#pragma unroll
    for (int e = t; e < NN; e += STPB) {
        float ti = target[e];
        int b = bucket_of(ti);
        int lo = g_offsets[b], hi = g_offsets[b + 1];
        int r = lo;
        for (int m = lo; m < hi; m++) {
            int j = g_members[m];
            float tj = target[j];
            if (tj < ti || (tj == ti && j < e)) r++;
        }
        g_ps[r] = pred[e];
    }
}

// ---- K2: triangular pair sweep over target-sorted preds ----
__global__ void __launch_bounds__(TPB)
pair_kernel() {
    __shared__ float sh[CH];
    const int rb = blockIdx.x;
    const int c  = blockIdx.y;
    const int r0 = rb * TPB;
    const int diagc = r0 >> 10;        // chunk containing this block's rows
    if (c > diagc) return;

    {
        const float4* g4 = reinterpret_cast<const float4*>(g_ps + c * CH);
        reinterpret_cast<float4*>(sh)[threadIdx.x] = g4[threadIdx.x];
    }
    __syncthreads();

    const int r = r0 + threadIdx.x;
    const float si = MARGIN - g_ps[r];
    const float4* sh4 = reinterpret_cast<const float4*>(sh);

    float acc;
    if (c < diagc) {
        float a0 = 0.f, a1 = 0.f, a2 = 0.f, a3 = 0.f;
#pragma unroll 8
        for (int k = 0; k < CH / 4; k++) {
            float4 v = sh4[k];
            a0 += fmaxf(si + v.x, 0.f);
            a1 += fmaxf(si + v.y, 0.f);
            a2 += fmaxf(si + v.z, 0.f);
            a3 += fmaxf(si + v.w, 0.f);
        }
        acc = (a0 + a1) + (a2 + a3);
    } else {
        const int lim = r - c * CH;    // in [0, 1023]
        float a0 = 0.f, a1 = 0.f, a2 = 0.f, a3 = 0.f;
        int k = 0;
        for (; k + 4 <= lim; k += 4) {
            float4 v = sh4[k >> 2];
            a0 += fmaxf(si + v.x, 0.f);
            a1 += fmaxf(si + v.y, 0.f);
            a2 += fmaxf(si + v.z, 0.f);
            a3 += fmaxf(si + v.w, 0.f);
        }
        acc = (a0 + a1) + (a2 + a3);
        for (; k < lim; k++) acc += fmaxf(si + sh[k], 0.f);
    }
    g_part[c][r] = acc;
}

// ---- K3: per-row loss + full mean, one block ----
__global__ void __launch_bounds__(STPB)
reduce_kernel(float* __restrict__ out) {
    __shared__ float sh[STPB];
    const int t = threadIdx.x;

    float local = 0.0f;
#pragma unroll
    for (int r = t; r < NN; r += STPB) {
        float s = 0.0f;
        const int cmax = r >> 10;
        for (int c = 0; c <= cmax; c++) s += g_part[c][r];
        local += (r > 0) ? (s / (float)r) : 0.0f;   // cnt_r == r
    }

    sh[t] = local;
    __syncthreads();
#pragma unroll
    for (int off = STPB / 2; off > 0; off >>= 1) {
        if (t < off) sh[t] += sh[t + off];
        __syncthreads();
    }
    if (t == 0) out[0] = sh[0] / (float)NN;
}

extern "C" void kernel_launch(void* const* d_in, const int* in_sizes, int n_in,
                              void* d_out, int out_size) {
    const float* pred   = (const float*)d_in[0];
    const float* target = (const float*)d_in[1];
    float* out = (float*)d_out;
    (void)in_sizes; (void)n_in; (void)out_size;

    sort_kernel<<<1, STPB>>>(pred, target);

    dim3 grid(NBLKROW, NCHUNK, 1);
    pair_kernel<<<grid, TPB>>>();

    reduce_kernel<<<1, STPB>>>(out);
}

// round 4
// speedup vs baseline: 1.0194x; 1.0194x over previous
#include <cuda_runtime.h>

// RankingLoss, N=16384 — single persistent kernel, software grid barriers.
// loss = (1/N) * sum_i [ cnt_i>0 ? (sum_{j: t_j<t_i} max(0, M - (p_i - p_j))) / cnt_i : 0 ]
//
// Phases (one launch, G=148 co-resident blocks):
//  1 hist        : bucket counts of target (targets ~ U[0,1), 16384 buckets)
//  2 scan        : block 0 -> exclusive bucket offsets
//  3 scatter     : (t_bits<<32|idx, pred) into bucket slots (atomic cursor)
//  4 rank        : exact in-bucket rank (order-invariant => deterministic) -> g_ps
//  5 pair        : row r: B_r = sum_{k<r} |si + p_k|  (max(x,0) = (x+|x|)/2)
//                  block 0 concurrently: exclusive prefix sums of g_ps -> g_pp
//  6 reduce      : row_sum = 0.5*(r*si + g_pp[r] + B_r); mean((r>0)? row_sum/r : 0)
//                  (also re-zeroes hist scratch for the next graph replay)

#define NN 16384
#define NBUCK 16384
#define G 148
#define TPB 256
#define CH 1024
#define NCHUNK (NN / CH)        // 16
#define NBLKROW (NN / TPB)      // 64
#define NTILE 544               // sum_{rb=0}^{63} ((rb>>2)+1)
#define MARGIN 0.1f

__device__ int      g_count[NBUCK];         // zero-initialized; re-zeroed each run
__device__ int      g_cursor[NBUCK];        // zero-initialized; re-zeroed each run
__device__ int      g_offsets[NBUCK + 1];
__device__ unsigned long long g_skey[NN];   // (target_bits << 32) | index
__device__ float    g_sval[NN];             // pred at scattered slot
__device__ float    g_ps[NN];               // pred in target-sorted order
__device__ float    g_pp[NN];               // exclusive prefix sums of g_ps
__device__ float    g_part[NCHUNK][NN];     // per-(chunk,row) abs-sum partials
__device__ float    g_blk[G];

__device__ unsigned          g_bar_cnt = 0;
__device__ volatile unsigned g_bar_gen = 0;

__device__ __forceinline__ void grid_bar() {
    __syncthreads();
    if (threadIdx.x == 0) {
        unsigned my = g_bar_gen;
        __threadfence();
        if (atomicAdd(&g_bar_cnt, 1) == (unsigned)(gridDim.x - 1)) {
            g_bar_cnt = 0;
            __threadfence();
            g_bar_gen = my + 1;
        } else {
            while (g_bar_gen == my) { }
        }
        __threadfence();
    }
    __syncthreads();
}

__device__ __forceinline__ int bucket_of(float t) {
    int b = (int)(t * (float)NBUCK);
    b = b < 0 ? 0 : (b > NBUCK - 1 ? NBUCK - 1 : b);
    return b;
}

__global__ void __launch_bounds__(TPB)
fused_kernel(const float* __restrict__ pred, const float* __restrict__ target,
             float* __restrict__ out) {
    __shared__ float shf[CH];       // pair-tile staging (4KB)
    __shared__ float sred[TPB];     // scans / reductions (1KB)

    const int t    = threadIdx.x;
    const int b    = blockIdx.x;
    const int gtid = b * TPB + t;
    const int GT   = G * TPB;       // 37888 threads

    // ---- Phase 1: histogram (g_count assumed zero at entry) ----
    for (int e = gtid; e < NN; e += GT)
        atomicAdd(&g_count[bucket_of(target[e])], 1);
    grid_bar();

    // ---- Phase 2: block 0 scans bucket counts -> exclusive offsets ----
    if (b == 0) {
        int* sscan = (int*)sred;
        const int per = NBUCK / TPB;      // 64 buckets per thread
        const int base = t * per;
        int s = 0;
#pragma unroll 8
        for (int k = 0; k < per; k++) s += g_count[base + k];
        sscan[t] = s;
        __syncthreads();
#pragma unroll
        for (int off = 1; off < TPB; off <<= 1) {
            int v = (t >= off) ? sscan[t - off] : 0;
            __syncthreads();
            sscan[t] += v;
            __syncthreads();
        }
        int run = sscan[t] - s;           // exclusive prefix of this segment
#pragma unroll 8
        for (int k = 0; k < per; k++) { g_offsets[base + k] = run; run += g_count[base + k]; }
        if (t == TPB - 1) g_offsets[NBUCK] = run;
    }
    grid_bar();

    // ---- Phase 3: scatter (key, pred) into bucket slots ----
    for (int e = gtid; e < NN; e += GT) {
        float tv = target[e];
        int bk = bucket_of(tv);
        int pos = g_offsets[bk] + atomicAdd(&g_cursor[bk], 1);
        g_skey[pos] = ((unsigned long long)__float_as_uint(tv) << 32) | (unsigned)e;
        g_sval[pos] = pred[e];
    }
    grid_bar();

    // ---- Phase 4: exact rank within bucket -> g_ps (order-invariant) ----
    for (int s0 = gtid; s0 < NN; s0 += GT) {
        unsigned long long key = g_skey[s0];
        float tv = __uint_as_float((unsigned)(key >> 32));
        int bk = bucket_of(tv);
        int lo = g_offsets[bk], hi = g_offsets[bk + 1];
        int r = lo;
        for (int m = lo; m < hi; m++) r += (g_skey[m] < key) ? 1 : 0;
        g_ps[r] = g_sval[s0];
    }
    grid_bar();

    // ---- Phase 5a: block 0 computes exclusive prefix sums of g_ps -> g_pp.
    //      Runs concurrently with phase 5b (both only READ g_ps). ----
    if (b == 0) {
        const int per = NN / TPB;         // 64
        const int base = t * per;
        float s = 0.0f;
#pragma unroll 8
        for (int k = 0; k < per; k++) s += g_ps[base + k];
        sred[t] = s;
        __syncthreads();
#pragma unroll
        for (int off = 1; off < TPB; off <<= 1) {
            float v = (t >= off) ? sred[t - off] : 0.0f;
            __syncthreads();
            sred[t] += v;
            __syncthreads();
        }
        float run = sred[t] - s;
#pragma unroll 8
        for (int k = 0; k < per; k++) { g_pp[base + k] = run; run += g_ps[base + k]; }
    }

    // Re-zero histogram scratch for the next graph replay (restores the
    // zero-at-entry invariant; nothing reads these until the next launch).
    for (int e = gtid; e < NBUCK; e += GT) { g_count[e] = 0; g_cursor[e] = 0; }

    // ---- Phase 5b: pair tiles. Row r accumulates B = sum_{k<r} |si + p_k|. ----
    for (int vid = b; vid < NTILE; vid += G) {
        // decode vid -> (rb, c): row-block rb has (rb>>2)+1 valid chunks
        int rb = 0, rem = vid;
        while (rem >= ((rb >> 2) + 1)) { rem -= (rb >> 2) + 1; rb++; }
        const int c = rem;
        const int diagc = rb >> 2;

        __syncthreads();   // protect shf from previous tile's readers
        ((float4*)shf)[t] = ((const float4*)(g_ps + c * CH))[t];
        __syncthreads();

        const int r = rb * TPB + t;
        const float si = MARGIN - g_ps[r];
        const float4* sh4 = (const float4*)shf;

        float a0 = 0.f, a1 = 0.f, a2 = 0.f, a3 = 0.f;
        if (c < diagc) {
#pragma unroll 8
            for (int k = 0; k < CH / 4; k++) {
                float4 v = sh4[k];
                a0 += fabsf(si + v.x);
                a1 += fabsf(si + v.y);
                a2 += fabsf(si + v.z);
                a3 += fabsf(si + v.w);
            }
        } else {
            const int lim = r - c * CH;   // in [0, 1023]
            int k = 0;
            for (; k + 4 <= lim; k += 4) {
                float4 v = sh4[k >> 2];
                a0 += fabsf(si + v.x);
                a1 += fabsf(si + v.y);
                a2 += fabsf(si + v.z);
                a3 += fabsf(si + v.w);
            }
            for (; k < lim; k++) a0 += fabsf(si + shf[k]);
        }
        g_part[c][r] = (a0 + a1) + (a2 + a3);
    }
    grid_bar();

    // ---- Phase 6: per-row loss + block partial sums ----
    {
        float per = 0.0f;
        const int r = gtid;               // GT > NN: at most one row per thread
        if (r > 0 && r < NN) {
            float B = 0.0f;
            const int cmax = r >> 10;
            for (int c = 0; c <= cmax; c++) B += g_part[c][r];
            const float si = MARGIN - g_ps[r];
            const float A = (float)r * si + g_pp[r];       // sum_{k<r} (si + p_k)
            const float rowsum = 0.5f * (A + B);           // sum of max(x, 0)
            per = rowsum / (float)r;                       // cnt_r == r
        }
        __syncthreads();                  // sred free (block 0 finished scan use)
        sred[t] = per;
        __syncthreads();
#pragma unroll
        for (int off = TPB / 2; off > 0; off >>= 1) {
            if (t < off) sred[t] += sred[t + off];
            __syncthreads();
        }
        if (t == 0) g_blk[b] = sred[0];
    }
    grid_bar();

    // ---- Final: block 0 thread 0 sums G partials (fixed order, deterministic) ----
    if (b == 0 && t == 0) {
        float tot = 0.0f;
        for (int i = 0; i < G; i++) tot += g_blk[i];
        out[0] = tot / (float)NN;
    }
}

extern "C" void kernel_launch(void* const* d_in, const int* in_sizes, int n_in,
                              void* d_out, int out_size) {
    const float* pred   = (const float*)d_in[0];
    const float* target = (const float*)d_in[1];
    float* out = (float*)d_out;
    (void)in_sizes; (void)n_in; (void)out_size;

    fused_kernel<<<G, TPB>>>(pred, target, out);
}

// round 7
// speedup vs baseline: 1.1799x; 1.1575x over previous
#include <cuda_runtime.h>

// RankingLoss, N=16384.
// loss = (1/N) * sum_i [ cnt_i>0 ? (sum_{j: t_j<t_i} max(0, M - (p_i - p_j))) / cnt_i : 0 ]
//
// K1 (148x1024, persistent, 3 grid barriers): bucket-rank sort by target ->
//     g_ps[r] = pred of r-th smallest target (exact in-bucket rank, order-
//     invariant => deterministic).
// K2 (64x16 x 256): triangular sweep, row r accumulates B_r = sum_{k<r} |si+p_k|
//     where si = M - p_r  (max(x,0) = (x+|x|)/2 -> 2 FADD/pair).
// K3 (1x1024): prefix sums of g_ps, row_sum = 0.5*(r*si + pp_r + B_r),
//     mean over rows (cnt_r == r); re-zeroes scratch for graph replay.

#define NN 16384
#define NBUCK 16384
#define G1 148
#define T1 1024
#define TPB 256
#define CH 1024
#define NCHUNK (NN / CH)        // 16
#define NBLKROW (NN / TPB)      // 64
#define MARGIN 0.1f

__device__ int      g_count[NBUCK];        // zero at entry; re-zeroed by K3
__device__ int      g_cursor[NBUCK];       // zero at entry; re-zeroed by K3
__device__ int      g_offsets[NBUCK + 1];
__device__ unsigned long long g_skey[NN];  // (target_bits << 32) | index
__device__ float    g_sval[NN];
__device__ float    g_ps[NN];              // pred in target-sorted order
__device__ float    g_pp[NN];              // exclusive prefix sums of g_ps
__device__ float    g_part[NCHUNK][NN];    // per-(chunk,row) abs-sum partials

__device__ unsigned          g_bar_cnt = 0;
__device__ volatile unsigned g_bar_gen = 0;

__device__ __forceinline__ void grid_bar() {
    __syncthreads();
    if (threadIdx.x == 0) {
        unsigned my = g_bar_gen;
        __threadfence();
        if (atomicAdd(&g_bar_cnt, 1) == (unsigned)(gridDim.x - 1)) {
            g_bar_cnt = 0;
            __threadfence();
            g_bar_gen = my + 1;
        } else {
            while (g_bar_gen == my) { }
        }
        __threadfence();
    }
    __syncthreads();
}

__device__ __forceinline__ int bucket_of(float t) {
    int b = (int)(t * (float)NBUCK);
    b = b < 0 ? 0 : (b > NBUCK - 1 ? NBUCK - 1 : b);
    return b;
}

// ---- K1: bucket-rank sort (persistent, high occupancy) ----
__global__ void __launch_bounds__(T1)
preprocess_kernel(const float* __restrict__ pred, const float* __restrict__ target) {
    __shared__ int sscan[T1];
    const int t = threadIdx.x;
    const int b = blockIdx.x;
    const int gtid = b * T1 + t;

    // Phase 1: histogram (g_count zero at entry).
    if (gtid < NN)
        atomicAdd(&g_count[bucket_of(target[gtid])], 1);
    grid_bar();

    // Phase 2: block 0 -> exclusive bucket offsets.
    if (b == 0) {
        const int per = NBUCK / T1;   // 16
        const int base = t * per;
        int loc[16];
        int s = 0;
#pragma unroll
        for (int k = 0; k < per; k++) { loc[k] = g_count[base + k]; s += loc[k]; }
        sscan[t] = s;
        __syncthreads();
#pragma unroll
        for (int off = 1; off < T1; off <<= 1) {
            int v = (t >= off) ? sscan[t - off] : 0;
            __syncthreads();
            sscan[t] += v;
            __syncthreads();
        }
        int run = sscan[t] - s;
#pragma unroll
        for (int k = 0; k < per; k++) { g_offsets[base + k] = run; run += loc[k]; }
        if (t == T1 - 1) g_offsets[NBUCK] = run;
    }
    grid_bar();

    // Phase 3: scatter (key, pred) into bucket segments (order arbitrary).
    if (gtid < NN) {
        float tv = target[gtid];
        int bk = bucket_of(tv);
        int pos = g_offsets[bk] + atomicAdd(&g_cursor[bk], 1);
        g_skey[pos] = ((unsigned long long)__float_as_uint(tv) << 32) | (unsigned)gtid;
        g_sval[pos] = pred[gtid];
    }
    grid_bar();

    // Phase 4: exact in-bucket rank (order-invariant => deterministic) -> g_ps.
    if (gtid < NN) {
        unsigned long long key = g_skey[gtid];
        float tv = __uint_as_float((unsigned)(key >> 32));
        int bk = bucket_of(tv);
        int lo = g_offsets[bk], hi = g_offsets[bk + 1];
        int r = lo;
        for (int m = lo; m < hi; m++) r += (g_skey[m] < key) ? 1 : 0;
        g_ps[r] = g_sval[gtid];
    }
}

// ---- K2: triangular pair sweep (2 FADD/pair via abs identity) ----
__global__ void __launch_bounds__(TPB)
pair_kernel() {
    __shared__ float sh[CH];
    const int rb = blockIdx.x;
    const int c  = blockIdx.y;
    const int diagc = rb >> 2;         // chunk containing this block's rows
    if (c > diagc) return;

    {
        const float4* g4 = reinterpret_cast<const float4*>(g_ps + c * CH);
        reinterpret_cast<float4*>(sh)[threadIdx.x] = g4[threadIdx.x];
    }
    __syncthreads();

    const int r = rb * TPB + threadIdx.x;
    const float si = MARGIN - g_ps[r];
    const float4* sh4 = reinterpret_cast<const float4*>(sh);

    float a0 = 0.f, a1 = 0.f, a2 = 0.f, a3 = 0.f;
    if (c < diagc) {
#pragma unroll 8
        for (int k = 0; k < CH / 4; k++) {
            float4 v = sh4[k];
            a0 += fabsf(si + v.x);
            a1 += fabsf(si + v.y);
            a2 += fabsf(si + v.z);
            a3 += fabsf(si + v.w);
        }
    } else {
        const int lim = r - c * CH;    // in [0, 1023]
        int k = 0;
        for (; k + 4 <= lim; k += 4) {
            float4 v = sh4[k >> 2];
            a0 += fabsf(si + v.x);
            a1 += fabsf(si + v.y);
            a2 += fabsf(si + v.z);
            a3 += fabsf(si + v.w);
        }
        for (; k < lim; k++) a0 += fabsf(si + sh[k]);
    }
    g_part[c][r] = (a0 + a1) + (a2 + a3);
}

// ---- K3: prefix + per-row loss + mean; restore scratch zeros ----
__global__ void __launch_bounds__(T1)
reduce_kernel(float* __restrict__ out) {
    __shared__ float sh[T1];
    const int t = threadIdx.x;

    // Exclusive prefix sums of g_ps -> g_pp (fixed order => deterministic).
    {
        const int per = NN / T1;       // 16
        const int base = t * per;
        float loc[16];
        float s = 0.0f;
#pragma unroll
        for (int k = 0; k < per; k++) { loc[k] = g_ps[base + k]; s += loc[k]; }
        sh[t] = s;
        __syncthreads();
#pragma unroll
        for (int off = 1; off < T1; off <<= 1) {
            float v = (t >= off) ? sh[t - off] : 0.0f;
            __syncthreads();
            sh[t] += v;
            __syncthreads();
        }
        float run = sh[t] - s;
#pragma unroll
        for (int k = 0; k < per; k++) { g_pp[base + k] = run; run += loc[k]; }
    }
    __syncthreads();

    // Per-row loss; row_sum = 0.5 * (r*si + pp_r + B_r); cnt_r == r.
    float local = 0.0f;
    for (int r = t; r < NN; r += T1) {
        if (r == 0) continue;
        float B = 0.0f;
        const int cmax = r >> 10;
        for (int c = 0; c <= cmax; c++) B += g_part[c][r];
        const float si = MARGIN - g_ps[r];
        const float A = (float)r * si + g_pp[r];
        local += 0.5f * (A + B) / (float)r;
    }
    __syncthreads();
    sh[t] = local;
    __syncthreads();
#pragma unroll
    for (int off = T1 / 2; off > 0; off >>= 1) {
        if (t < off) sh[t] += sh[t + off];
        __syncthreads();
    }
    if (t == 0) out[0] = sh[0] / (float)NN;

    // Restore zero-at-entry invariant for the next graph replay.
    {
        int4 z = make_int4(0, 0, 0, 0);
        int4* c4 = reinterpret_cast<int4*>(g_count);
        int4* u4 = reinterpret_cast<int4*>(g_cursor);
        for (int k = t; k < NBUCK / 4; k += T1) { c4[k] = z; u4[k] = z; }
    }
}

extern "C" void kernel_launch(void* const* d_in, const int* in_sizes, int n_in,
                              void* d_out, int out_size) {
    const float* pred   = (const float*)d_in[0];
    const float* target = (const float*)d_in[1];
    float* out = (float*)d_out;
    (void)in_sizes; (void)n_in; (void)out_size;

    preprocess_kernel<<<G1, T1>>>(pred, target);

    dim3 grid(NBLKROW, NCHUNK, 1);
    pair_kernel<<<grid, TPB>>>();

    reduce_kernel<<<1, T1>>>(out);
}

// round 9
// speedup vs baseline: 1.4041x; 1.1900x over previous
#include <cuda_runtime.h>

// RankingLoss, N=16384.
// loss = (1/N) * sum_i [ cnt_i>0 ? (sum_{j: t_j<t_i} max(0, M - (p_i - p_j))) / cnt_i : 0 ]
//
// Rank by target (bucket sort, targets ~ U[0,1)); in sorted order cnt_r == r
// and the valid set is {k < r}. Split {k < r} into full 1024-chunks (closed
// form on pred-sorted chunk + prefix sums, via binary search) plus the
// diagonal chunk (element loop, abs identity). 5 launches; single-block
// stages run in the last-arriving block of the preceding wide kernel.

#define NN 16384
#define NBUCK 16384
#define CH 1024
#define NCHUNK 16
#define MARGIN 0.1f

__device__ int      g_count[NBUCK];          // zero at entry; re-zeroed at end
__device__ int      g_cursor[NBUCK];         // zero at entry; re-zeroed at end
__device__ int      g_offsets[NBUCK + 1];
__device__ unsigned long long g_skey[NN];    // (target_bits << 32) | index
__device__ float    g_sval[NN];
__device__ float    g_ps[NN];                // preds in target-sorted order
__device__ float    g_diag[NN];              // per-row diagonal hinge sum
__device__ float    g_cps[NCHUNK][CH];       // per-chunk pred-sorted values
__device__ float    g_cpp[NCHUNK][CH + 1];   // per-chunk exclusive prefix sums
__device__ float    g_part[NCHUNK - 1][NN];  // full-chunk contributions, c<15
__device__ unsigned g_done1 = 0;             // arrival counters (self-resetting)
__device__ unsigned g_done5 = 0;

__device__ __forceinline__ int bucket_of(float t) {
    int b = (int)(t * (float)NBUCK);
    return b < 0 ? 0 : (b > NBUCK - 1 ? NBUCK - 1 : b);
}

// ---- K1: histogram; last block scans bucket counts -> exclusive offsets ----
__global__ void __launch_bounds__(1024)
hist_kernel(const float* __restrict__ target) {
    __shared__ int sscan[1024];
    __shared__ unsigned s_last;
    const int t = threadIdx.x;
    const int gtid = blockIdx.x * 1024 + t;

    atomicAdd(&g_count[bucket_of(target[gtid])], 1);

    __threadfence();
    __syncthreads();
    if (t == 0) s_last = (atomicAdd(&g_done1, 1) == gridDim.x - 1);
    __syncthreads();
    if (!s_last) return;
    if (t == 0) g_done1 = 0;          // reset for next graph replay
    __threadfence();

    // Scan 16384 counts with 1024 threads (16 each) + Hillis-Steele.
    const int base = t * 16;
    int loc[16];
    int s = 0;
#pragma unroll
    for (int k = 0; k < 16; k++) { loc[k] = g_count[base + k]; s += loc[k]; }
    sscan[t] = s;
    __syncthreads();
    for (int off = 1; off < 1024; off <<= 1) {
        int v = (t >= off) ? sscan[t - off] : 0;
        __syncthreads();
        sscan[t] += v;
        __syncthreads();
    }
    int run = sscan[t] - s;
#pragma unroll
    for (int k = 0; k < 16; k++) { g_offsets[base + k] = run; run += loc[k]; }
    if (t == 1023) g_offsets[NBUCK] = run;
}

// ---- K2: scatter (key, pred) into bucket segments (order arbitrary) ----
__global__ void __launch_bounds__(1024)
scatter_kernel(const float* __restrict__ pred, const float* __restrict__ target) {
    const int i = blockIdx.x * 1024 + threadIdx.x;
    float tv = target[i];
    int b = bucket_of(tv);
    int pos = g_offsets[b] + atomicAdd(&g_cursor[b], 1);
    // targets in [0,1): sign bit 0, so float bits compare correctly as uint
    g_skey[pos] = ((unsigned long long)__float_as_uint(tv) << 32) | (unsigned)i;
    g_sval[pos] = pred[i];
}

// ---- K3: exact in-bucket rank (order-invariant => deterministic) -> g_ps ----
__global__ void __launch_bounds__(1024)
rank_kernel() {
    const int i = blockIdx.x * 1024 + threadIdx.x;
    unsigned long long key = g_skey[i];
    float tv = __uint_as_float((unsigned)(key >> 32));
    int b = bucket_of(tv);
    int lo = g_offsets[b], hi = g_offsets[b + 1];
    int r = lo;
    for (int m = lo; m < hi; m++) r += (g_skey[m] < key) ? 1 : 0;
    g_ps[r] = g_sval[i];
}

// ---- K4: per chunk: y=0 diagonal sums; y=1 pred-sort + prefix sums ----
__global__ void __launch_bounds__(1024)
chunk_kernel() {
    __shared__ float sh[CH];
    __shared__ float sp[CH];
    const int c = blockIdx.x;
    const int t = threadIdx.x;

    sh[t] = g_ps[c * CH + t];
    __syncthreads();

    if (blockIdx.y == 0) {
        // Diagonal: row r=c*CH+t needs sum_{k<t} max(0, si + sh[k]).
        // Use max(x,0) = (x+|x|)/2: linear part via in-chunk prefix scan.
        float v = sh[t];
        sp[t] = v;
        __syncthreads();
        for (int off = 1; off < CH; off <<= 1) {
            float a = (t >= off) ? sp[t - off] : 0.0f;
            __syncthreads();
            sp[t] += a;
            __syncthreads();
        }
        const float si = MARGIN - v;
        float a0 = 0.f, a1 = 0.f, a2 = 0.f, a3 = 0.f;
        const float4* s4 = (const float4*)sh;
        int k = 0;
        for (; k + 4 <= t; k += 4) {
            float4 w = s4[k >> 2];
            a0 += fabsf(si + w.x);
            a1 += fabsf(si + w.y);
            a2 += fabsf(si + w.z);
            a3 += fabsf(si + w.w);
        }
        float B = (a0 + a1) + (a2 + a3);
        for (; k < t; k++) B += fabsf(si + sh[k]);
        float lin = (float)t * si + (sp[t] - v);   // t*si + sum_{k<t} p_k
        g_diag[c * CH + t] = 0.5f * (lin + B);
    } else {
        // Bitonic sort ascending (1024 elems, 1 per thread).
        for (int k = 2; k <= CH; k <<= 1) {
            for (int j = k >> 1; j > 0; j >>= 1) {
                __syncthreads();
                int ixj = t ^ j;
                if (ixj > t) {
                    float a = sh[t], b = sh[ixj];
                    bool up = ((t & k) == 0);
                    if (up ? (a > b) : (a < b)) { sh[t] = b; sh[ixj] = a; }
                }
            }
        }
        __syncthreads();
        float v = sh[t];
        sp[t] = v;
        __syncthreads();
        for (int off = 1; off < CH; off <<= 1) {
            float a = (t >= off) ? sp[t - off] : 0.0f;
            __syncthreads();
            sp[t] += a;
            __syncthreads();
        }
        g_cps[c][t] = v;
        g_cpp[c][t + 1] = sp[t];       // inclusive -> exclusive shifted by 1
        if (t == 0) g_cpp[c][0] = 0.0f;
    }
}

// ---- K5: full-chunk closed forms; last block: reduce + output + re-zero ----
__global__ void __launch_bounds__(1024)
pair_kernel(float* __restrict__ out) {
    __shared__ float ssp[CH];
    __shared__ float spp[CH + 1];
    __shared__ unsigned s_last;
    const int cb = blockIdx.x;       // row chunk 0..15
    const int c  = blockIdx.y;       // pred chunk 0..14 (active iff c < cb)
    const int t  = threadIdx.x;

    if (c < cb) {
        ssp[t] = g_cps[c][t];
        spp[t] = g_cpp[c][t];
        if (t == 0) spp[CH] = g_cpp[c][CH];
        __syncthreads();

        const int r = cb * CH + t;
        const float si  = MARGIN - g_ps[r];
        const float key = -si;
        // m = #{elements <= key} in sorted chunk
        int m = 0;
#pragma unroll
        for (int w = CH >> 1; w > 0; w >>= 1) {
            int nm = m + w;
            if (ssp[nm - 1] <= key) m = nm;
        }
        if (m == CH - 1 && ssp[CH - 1] <= key) m = CH;
        g_part[c][r] = (float)(CH - m) * si + (spp[CH] - spp[m]);
        __threadfence();
    }

    __syncthreads();
    if (t == 0) s_last = (atomicAdd(&g_done5, 1) == gridDim.x * gridDim.y - 1);
    __syncthreads();
    if (!s_last) return;
    if (t == 0) g_done5 = 0;          // reset for next graph replay
    __threadfence();

    // Final reduce (fixed order => deterministic regardless of which block).
    float local = 0.0f;
    for (int r = t; r < NN; r += 1024) {
        if (r == 0) continue;
        const int dc = r >> 10;
        float S = 0.0f;
        for (int cc = 0; cc < dc; cc++) S += g_part[cc][r];
        S += g_diag[r];
        local += S / (float)r;        // cnt_r == r
    }
    __syncthreads();
    spp[t] = local;
    __syncthreads();
    for (int off = 512; off > 0; off >>= 1) {
        if (t < off) spp[t] += spp[t + off];
        __syncthreads();
    }
    if (t == 0) out[0] = spp[0] / (float)NN;

    // Restore zero-at-entry invariant for next replay.
    int4 z = make_int4(0, 0, 0, 0);
    int4* c4 = (int4*)g_count;
    int4* u4 = (int4*)g_cursor;
    for (int k = t; k < NBUCK / 4; k += 1024) { c4[k] = z; u4[k] = z; }
}

extern "C" void kernel_launch(void* const* d_in, const int* in_sizes, int n_in,
                              void* d_out, int out_size) {
    const float* pred   = (const float*)d_in[0];
    const float* target = (const float*)d_in[1];
    float* out = (float*)d_out;
    (void)in_sizes; (void)n_in; (void)out_size;

    hist_kernel   <<<NN / 1024, 1024>>>(target);
    scatter_kernel<<<NN / 1024, 1024>>>(pred, target);
    rank_kernel   <<<NN / 1024, 1024>>>();
    chunk_kernel  <<<dim3(NCHUNK, 2), 1024>>>();
    pair_kernel   <<<dim3(NCHUNK, NCHUNK - 1), 1024>>>(out);
}

// round 10
// speedup vs baseline: 1.8652x; 1.3284x over previous
#include <cuda_runtime.h>

// RankingLoss, N=16384 — single persistent kernel, 16 blocks x 1024.
// loss = (1/N) * sum_i [ cnt_i>0 ? (sum_{j: t_j<t_i} max(0, M - (p_i - p_j))) / cnt_i : 0 ]
//
// Rank points by target (2048-bucket sort, targets ~ U[0,1)); in sorted order
// cnt_r == r and the valid set is {k < r}. Decompose {k < r}:
//   - full preceding 1024-chunks: closed form on pred-sorted chunk + prefix
//     sums (binary search):  sum max(0,si+p) = (n-m)*si + (tot - P[m]), exact.
//   - diagonal chunk: full preceding 32-subwarps via the same closed form on
//     warp-sorted subarrays; own subwarp via a 32-step shfl hinge loop.
// Chunk sort = register bitonic-32 per warp (shfl, 0 barriers) + 5 merge-path
// rounds (1 barrier each). All reductions fixed-order => deterministic.

#define NN 16384
#define NB 2048
#define GBLK 16
#define TPB 1024
#define CH 1024
#define NCHUNK 16
#define NTILES 136              // 120 closed (c<cb) + 16 diagonal
#define MARGIN 0.1f
#define FULLMASK 0xffffffffu

__device__ int      g_count[NB];           // zero at entry; re-zeroed in P2
__device__ int      g_cursor[NB];          // zero at entry; re-zeroed in P3
__device__ int      g_offsets[NB + 1];
__device__ unsigned long long g_skey[NN];  // (target_bits << 32) | index
__device__ float    g_sval[NN];
__device__ float    g_ps[NN];              // preds in target-sorted order
__device__ float    g_ws[NN];              // per-subwarp sorted preds
__device__ float    g_wp[NN];              // per-subwarp exclusive prefix
__device__ float    g_wtot[NN / 32];       // per-subwarp totals
__device__ float    g_cps[NCHUNK][CH];     // per-chunk pred-sorted values
__device__ float    g_cpp[NCHUNK][CH + 1]; // per-chunk exclusive prefix (+tot)
__device__ float    g_part[NCHUNK - 1][NN];
__device__ float    g_diag[NN];
__device__ float    g_blk[GBLK];
__device__ unsigned          g_bar_cnt = 0;
__device__ volatile unsigned g_bar_gen = 0;

__device__ __forceinline__ void grid_bar() {
    __syncthreads();
    if (threadIdx.x == 0) {
        unsigned my = g_bar_gen;
        __threadfence();
        if (atomicAdd(&g_bar_cnt, 1) == (unsigned)(GBLK - 1)) {
            g_bar_cnt = 0;
            __threadfence();
            g_bar_gen = my + 1;
        } else {
            while (g_bar_gen == my) { }
        }
        __threadfence();
    }
    __syncthreads();
}

__device__ __forceinline__ int bucket_of(float t) {
    int b = (int)(t * (float)NB);
    return b < 0 ? 0 : (b > NB - 1 ? NB - 1 : b);
}

// Merge-path round: merge pairs of sorted runs of length n=2^lg from src into
// dst (runs contiguous). Left-run elems use strict '<' count in sibling; right
// use '<=' — bijective output slots even with duplicate values.
__device__ __forceinline__ void merge_round(const float* src, float* dst,
                                            int lg, int t) {
    const int n = 1 << lg;
    const float x = src[t];
    const int runid = t >> lg;
    const int i = t & (n - 1);
    const int sib = (runid ^ 1) << lg;
    int m = 0;
    if ((runid & 1) == 0) {
        for (int w = n >> 1; w > 0; w >>= 1)
            if (src[sib + m + w - 1] < x) m += w;
        if (m == n - 1 && src[sib + n - 1] < x) m = n;
    } else {
        for (int w = n >> 1; w > 0; w >>= 1)
            if (src[sib + m + w - 1] <= x) m += w;
        if (m == n - 1 && src[sib + n - 1] <= x) m = n;
    }
    const int pairbase = t & ~((n << 1) - 1);
    dst[pairbase + i + m] = x;
}

__global__ void __launch_bounds__(TPB)
fused_kernel(const float* __restrict__ pred, const float* __restrict__ target,
             float* __restrict__ out) {
    __shared__ float sA[CH];
    __shared__ float sB[CH + 8];
    __shared__ float sW[32];
    __shared__ float sS[32];

    const int t    = threadIdx.x;
    const int b    = blockIdx.x;
    const int gtid = b * TPB + t;
    const int lane = t & 31;
    const int w    = t >> 5;

    // ---- P0: histogram (g_count zero at entry) ----
    atomicAdd(&g_count[bucket_of(target[gtid])], 1);
    grid_bar();

    // ---- P1: block 0 scans 2048 counts -> exclusive offsets ----
    if (b == 0) {
        int c0 = g_count[2 * t], c1 = g_count[2 * t + 1];
        int s = c0 + c1;
        int v = s;
        for (int d = 1; d < 32; d <<= 1) {
            int o = __shfl_up_sync(FULLMASK, v, d);
            if (lane >= d) v += o;
        }
        if (lane == 31) reinterpret_cast<int*>(sS)[w] = v;
        __syncthreads();
        if (w == 0) {
            int x = reinterpret_cast<int*>(sS)[lane];
            for (int d = 1; d < 32; d <<= 1) {
                int o = __shfl_up_sync(FULLMASK, x, d);
                if (lane >= d) x += o;
            }
            reinterpret_cast<int*>(sW)[lane] = x;
        }
        __syncthreads();
        int woff = (w == 0) ? 0 : reinterpret_cast<int*>(sW)[w - 1];
        int excl = woff + v - s;
        g_offsets[2 * t]     = excl;
        g_offsets[2 * t + 1] = excl + c0;
        if (t == TPB - 1) g_offsets[NB] = excl + s;
    }
    grid_bar();

    // ---- P2: scatter (key, pred) into bucket slots; re-zero g_count ----
    {
        float tv = target[gtid];
        int bk = bucket_of(tv);
        int pos = g_offsets[bk] + atomicAdd(&g_cursor[bk], 1);
        g_skey[pos] = ((unsigned long long)__float_as_uint(tv) << 32) | (unsigned)gtid;
        g_sval[pos] = pred[gtid];
        if (gtid < NB) g_count[gtid] = 0;
    }
    grid_bar();

    // ---- P3: exact in-bucket rank (order-invariant) -> g_ps; zero cursor ----
    {
        unsigned long long key = g_skey[gtid];
        float tv = __uint_as_float((unsigned)(key >> 32));
        int bk = bucket_of(tv);
        int lo = g_offsets[bk], hi = g_offsets[bk + 1];
        int r = lo;
        for (int m = lo; m < hi; m++) r += (g_skey[m] < key) ? 1 : 0;
        g_ps[r] = g_sval[gtid];
        if (gtid < NB) g_cursor[gtid] = 0;
    }
    grid_bar();

    // ---- P4: per-chunk sorted structures (block b = chunk b) ----
    {
        const float pown = g_ps[b * CH + t];

        // Register bitonic sort of each 32-subwarp (ascending), zero barriers.
        float p = pown;
#pragma unroll
        for (int k = 2; k <= 32; k <<= 1) {
#pragma unroll
            for (int j = k >> 1; j > 0; j >>= 1) {
                float o = __shfl_xor_sync(FULLMASK, p, j);
                bool up  = ((lane & k) == 0);
                bool low = ((lane & j) == 0);
                float mn = fminf(p, o), mx = fmaxf(p, o);
                p = (up == low) ? mn : mx;
            }
        }
        // Warp inclusive scan of sorted values.
        float v = p;
        for (int d = 1; d < 32; d <<= 1) {
            float o = __shfl_up_sync(FULLMASK, v, d);
            if (lane >= d) v += o;
        }
        float wt = __shfl_sync(FULLMASK, v, 31);
        g_ws[b * CH + t] = p;
        g_wp[b * CH + t] = v - p;            // exclusive prefix
        if (lane == 31) g_wtot[b * 32 + w] = wt;

        sA[t] = p;                            // 32 sorted runs of 32
        __syncthreads();
        merge_round(sA, sB, 5, t); __syncthreads();
        merge_round(sB, sA, 6, t); __syncthreads();
        merge_round(sA, sB, 7, t); __syncthreads();
        merge_round(sB, sA, 8, t); __syncthreads();
        merge_round(sA, sB, 9, t); __syncthreads();   // sorted 1024 in sB

        // Block exclusive prefix of sorted chunk.
        float sv = sB[t];
        float iv = sv;
        for (int d = 1; d < 32; d <<= 1) {
            float o = __shfl_up_sync(FULLMASK, iv, d);
            if (lane >= d) iv += o;
        }
        if (lane == 31) sW[w] = iv;
        __syncthreads();
        if (w == 0) {
            float x = sW[lane];
            for (int d = 1; d < 32; d <<= 1) {
                float o = __shfl_up_sync(FULLMASK, x, d);
                if (lane >= d) x += o;
            }
            sS[lane] = x;
        }
        __syncthreads();
        float woff = (w == 0) ? 0.0f : sS[w - 1];
        float excl = woff + iv - sv;
        g_cps[b][t] = sv;
        g_cpp[b][t] = excl;
        if (t == TPB - 1) g_cpp[b][CH] = excl + sv;
    }
    grid_bar();

    // ---- P5: 136 tiles over 16 blocks ----
    for (int tile = b; tile < NTILES; tile += GBLK) {
        int cb, c;
        if (tile < 120) {                      // closed tiles, (cb, c<cb)
            cb = 1; int base = 0;
            while (tile >= base + cb) { base += cb; cb++; }
            c = tile - base;
        } else { cb = tile - 120; c = cb; }    // diagonal tiles

        __syncthreads();                        // smem reuse fence
        if (c < cb) {
            sA[t] = g_cps[c][t];
            sB[t] = g_cpp[c][t];
            if (t == 0) sB[CH] = g_cpp[c][CH];
            __syncthreads();

            const int r = cb * CH + t;
            const float si = MARGIN - g_ps[r];
            const float key = -si;
            int m = 0;
#pragma unroll
            for (int ws2 = CH >> 1; ws2 > 0; ws2 >>= 1)
                if (sA[m + ws2 - 1] <= key) m += ws2;
            if (m == CH - 1 && sA[CH - 1] <= key) m = CH;
            g_part[c][r] = (float)(CH - m) * si + (sB[CH] - sB[m]);
        } else {
            sA[t] = g_ws[cb * CH + t];
            sB[t] = g_wp[cb * CH + t];
            if (t < 32) sW[t] = g_wtot[cb * 32 + t];
            __syncthreads();

            const int r = cb * CH + t;
            const float pown = g_ps[r];
            const float si = MARGIN - pown;
            const float key = -si;
            float acc = 0.0f;
            for (int w2 = 0; w2 < w; w2++) {   // full preceding subwarps
                const int bs = w2 * 32;
                int m = 0;
#pragma unroll
                for (int ws2 = 16; ws2 > 0; ws2 >>= 1)
                    if (sA[bs + m + ws2 - 1] <= key) m += ws2;
                if (m == 31 && sA[bs + 31] <= key) m = 32;
                float Pm = (m < 32) ? sB[bs + m] : sW[w2];
                acc += (float)(32 - m) * si + (sW[w2] - Pm);
            }
#pragma unroll
            for (int k2 = 0; k2 < 32; k2++) {  // own subwarp, target order
                float o = __shfl_sync(FULLMASK, pown, k2);
                if (k2 < lane) acc += fmaxf(si + o, 0.0f);
            }
            g_diag[r] = acc;
        }
    }
    grid_bar();

    // ---- P6: per-row loss + block partials ----
    {
        const int r = b * CH + t;
        float S = g_diag[r];
        for (int c2 = 0; c2 < b; c2++) S += g_part[c2][r];
        float per = (r > 0) ? S / (float)r : 0.0f;   // cnt_r == r

        float v = per;
        for (int d = 16; d > 0; d >>= 1) v += __shfl_down_sync(FULLMASK, v, d);
        __syncthreads();
        if (lane == 0) sW[w] = v;
        __syncthreads();
        if (w == 0) {
            float x = sW[lane];
            for (int d = 16; d > 0; d >>= 1) x += __shfl_down_sync(FULLMASK, x, d);
            if (lane == 0) g_blk[b] = x;
        }
    }
    grid_bar();

    // ---- Final: fixed-order sum of 16 partials ----
    if (b == 0 && t == 0) {
        float tot = 0.0f;
        for (int i = 0; i < GBLK; i++) tot += g_blk[i];
        out[0] = tot / (float)NN;
    }
}

extern "C" void kernel_launch(void* const* d_in, const int* in_sizes, int n_in,
                              void* d_out, int out_size) {
    const float* pred   = (const float*)d_in[0];
    const float* target = (const float*)d_in[1];
    float* out = (float*)d_out;
    (void)in_sizes; (void)n_in; (void)out_size;

    fused_kernel<<<GBLK, TPB>>>(pred, target, out);
}